// round 2
// baseline (speedup 1.0000x reference)
#include <cuda_runtime.h>
#include <math.h>

#define NN 6000
#define EE 120000
#define DD 128
#define DE 128
#define HH 4
#define LL 2
#define CC 384      // 2*DD + DE
#define HD 512      // HH*DD
#define D4 512      // 4*DD

// ---------------- scratch (device globals; no allocation) ----------------
__device__ float    g_feat[(size_t)EE * CC];     // [E, 384]
__device__ float    g_t1[(size_t)EE * DD];
__device__ float    g_t2[(size_t)EE * DD];
__device__ float    g_nupd[(size_t)EE * DD];     // nupd, later eu
__device__ float    g_eattr[(size_t)EE * DE];
__device__ float    g_scores[(size_t)EE * HH];
__device__ float    g_att[(size_t)EE * HH];
__device__ unsigned g_smaxu[NN * HH];
__device__ float    g_norm[NN * HH];
__device__ float    g_agg[(size_t)NN * HD];
__device__ float    g_nodes[NN * DD];
__device__ float    g_upd[NN * DD];
__device__ float    g_dense[(size_t)NN * D4];
__device__ float    g_dense2[NN * DD];
__device__ float    g_Wa[(size_t)LL * CC * HD];  // packed attention weights [l][c][h*D+d]

// ---------------- helpers ----------------
__device__ __forceinline__ float gelu_f(float x) {
    return 0.5f * x * (1.0f + erff(x * 0.70710678118654752440f));
}
__device__ __forceinline__ unsigned f2u(float f) {
    unsigned u = __float_as_uint(f);
    return (u & 0x80000000u) ? ~u : (u | 0x80000000u);
}
__device__ __forceinline__ float u2f(unsigned u) {
    return (u & 0x80000000u) ? __uint_as_float(u & 0x7fffffffu) : __uint_as_float(~u);
}

// ---------------- small kernels ----------------
__global__ void pack_wa(const float* __restrict__ aW) {
    int i = blockIdx.x * blockDim.x + threadIdx.x;
    if (i >= LL * HH * CC * DD) return;
    int d = i % DD;
    int c = (i / DD) % CC;
    int h = (i / (DD * CC)) % HH;
    int l = i / (DD * CC * HH);
    g_Wa[((size_t)l * CC + c) * HD + h * DD + d] = aW[i];
}

__global__ void node_embed(const int* __restrict__ seq, const float* __restrict__ emb) {
    int i = blockIdx.x * blockDim.x + threadIdx.x;
    if (i < NN * DD) g_nodes[i] = emb[seq[i / DD] * DD + (i % DD)];
}

__global__ void edge_init(const float* __restrict__ dist,
                          const float* __restrict__ W, const float* __restrict__ b) {
    int e = blockIdx.x;
    int t = threadIdx.x;
    __shared__ float rbf[16];
    if (t < 16) {
        float mu = 2.0f + (20.0f / 15.0f) * (float)t;
        float z = (dist[e] - mu) * (1.0f / 1.25f);
        rbf[t] = expf(-z * z) + 1e-8f;
    }
    __syncthreads();
    float acc = b[t];
#pragma unroll
    for (int k = 0; k < 16; k++) acc = fmaf(rbf[k], W[k * DE + t], acc);
    g_eattr[(size_t)e * DE + t] = acc;
}

__global__ void build_feat(const int* __restrict__ src, const int* __restrict__ snk) {
    int idx = blockIdx.x * blockDim.x + threadIdx.x;   // over EE*96 float4 slots
    if (idx >= EE * 96) return;
    int e = idx / 96;
    int j = idx % 96;
    float4 v;
    if (j < 32)       v = ((const float4*)g_nodes)[src[e] * 32 + j];
    else if (j < 64)  v = ((const float4*)g_nodes)[snk[e] * 32 + (j - 32)];
    else              v = ((const float4*)g_eattr)[(size_t)e * 32 + (j - 64)];
    ((float4*)g_feat)[(size_t)e * 96 + j] = v;
}

__global__ void init_scores(const float* __restrict__ aAb) {
    int i = blockIdx.x * blockDim.x + threadIdx.x;
    if (i < EE * HH) g_scores[i] = aAb[i % HH];
}

__global__ void smax_init() {
    int i = blockIdx.x * blockDim.x + threadIdx.x;
    if (i < NN * HH) { g_smaxu[i] = 0u; g_norm[i] = 0.0f; }
}

__global__ void smax_atomic(const int* __restrict__ snk) {
    int i = blockIdx.x * blockDim.x + threadIdx.x;
    if (i >= EE * HH) return;
    int e = i / HH, h = i % HH;
    atomicMax(&g_smaxu[snk[e] * HH + h], f2u(g_scores[i]));
}

__global__ void att_kernel(const int* __restrict__ snk) {
    int i = blockIdx.x * blockDim.x + threadIdx.x;
    if (i >= EE * HH) return;
    int e = i / HH, h = i % HH;
    int s = snk[e];
    float a = expf(g_scores[i] - u2f(g_smaxu[s * HH + h]));
    g_att[i] = a;
    atomicAdd(&g_norm[s * HH + h], a + 1e-12f);
}

__global__ void norm_att(const int* __restrict__ snk) {
    int i = blockIdx.x * blockDim.x + threadIdx.x;
    if (i >= EE * HH) return;
    int e = i / HH, h = i % HH;
    g_att[i] = g_att[i] / g_norm[snk[e] * HH + h];
}

__global__ void zero_agg() {
    int i = blockIdx.x * blockDim.x + threadIdx.x;
    if (i < NN * HD) g_agg[i] = 0.0f;
}

__global__ void aggregate(const int* __restrict__ snk) {
    int i = blockIdx.x * blockDim.x + threadIdx.x;   // over EE*DD
    if (i >= EE * DD) return;
    int e = i >> 7;
    int d = i & 127;
    float v = g_nupd[i];
    int s = snk[e];
    float4 w = *(const float4*)(g_att + e * 4);
    float* base = g_agg + (size_t)s * HD + d;
    atomicAdd(base,       w.x * v);
    atomicAdd(base + 128, w.y * v);
    atomicAdd(base + 256, w.z * v);
    atomicAdd(base + 384, w.w * v);
}

// LayerNorm over last dim (128). out = LN(A + R) * g + b, in-place safe per-row.
__global__ void ln_kernel(const float* __restrict__ A, const float* __restrict__ R,
                          const float* __restrict__ g, const float* __restrict__ b,
                          float* __restrict__ out) {
    int r = blockIdx.x;
    int t = threadIdx.x;
    float x = A[(size_t)r * DD + t] + R[(size_t)r * DD + t];
    float s = x;
#pragma unroll
    for (int o = 16; o > 0; o >>= 1) s += __shfl_xor_sync(0xffffffffu, s, o);
    __shared__ float ws[4], ws2[4];
    if ((t & 31) == 0) ws[t >> 5] = s;
    __syncthreads();
    float mean = (ws[0] + ws[1] + ws[2] + ws[3]) * (1.0f / DD);
    float dx = x - mean;
    float v = dx * dx;
#pragma unroll
    for (int o = 16; o > 0; o >>= 1) v += __shfl_xor_sync(0xffffffffu, v, o);
    if ((t & 31) == 0) ws2[t >> 5] = v;
    __syncthreads();
    float var = (ws2[0] + ws2[1] + ws2[2] + ws2[3]) * (1.0f / DD);
    out[(size_t)r * DD + t] = dx * (1.0f / sqrtf(var + 1e-5f)) * g[t] + b[t];
}

__global__ void copy_out(float* __restrict__ out) {
    int i = blockIdx.x * blockDim.x + threadIdx.x;
    if (i < NN * DD) out[i] = g_nodes[i];
    else if (i < NN * DD + EE * DE) out[i] = g_eattr[i - NN * DD];
}

// ---------------- GEMM: C[M,N] = act(A[M,K] @ B[K,N] + bias) ----------------
// 64x64 tiles, BK=16, 256 threads, 4x4 per thread. N multiple of 64, K multiple of 16.
template <int ACT>   // 0 none, 1 gelu, 2 lrelu
__global__ void __launch_bounds__(256) gemm_k(
    const float* __restrict__ A, int lda,
    const float* __restrict__ B, int ldb,
    const float* __restrict__ bias,
    float* __restrict__ C, int ldc,
    int M, int K) {
    __shared__ float As[16][68];
    __shared__ float Bs[16][68];
    const int tid = threadIdx.x;
    const int tx = tid & 15, ty = tid >> 4;
    const int row0 = blockIdx.y * 64, col0 = blockIdx.x * 64;
    float acc[4][4] = {};
    for (int k0 = 0; k0 < K; k0 += 16) {
#pragma unroll
        for (int i = 0; i < 4; i++) {
            int t = tid + i * 256;
            int r = t >> 4, c = t & 15;
            int gr = row0 + r;
            As[c][r] = (gr < M) ? A[(size_t)gr * lda + k0 + c] : 0.0f;
        }
#pragma unroll
        for (int i = 0; i < 4; i++) {
            int t = tid + i * 256;
            int r = t >> 6, c = t & 63;
            Bs[r][c] = B[(size_t)(k0 + r) * ldb + col0 + c];
        }
        __syncthreads();
#pragma unroll
        for (int kk = 0; kk < 16; kk++) {
            float4 a4 = *(const float4*)&As[kk][ty * 4];
            float4 b4 = *(const float4*)&Bs[kk][tx * 4];
            float a[4] = {a4.x, a4.y, a4.z, a4.w};
            float b[4] = {b4.x, b4.y, b4.z, b4.w};
#pragma unroll
            for (int i = 0; i < 4; i++)
#pragma unroll
                for (int j = 0; j < 4; j++)
                    acc[i][j] = fmaf(a[i], b[j], acc[i][j]);
        }
        __syncthreads();
    }
#pragma unroll
    for (int i = 0; i < 4; i++) {
        int gr = row0 + ty * 4 + i;
        if (gr >= M) continue;
#pragma unroll
        for (int j = 0; j < 4; j++) {
            int gc = col0 + tx * 4 + j;
            float v = acc[i][j] + bias[gc];
            if (ACT == 1) v = gelu_f(v);
            else if (ACT == 2) v = (v > 0.0f) ? v : 0.2f * v;
            C[(size_t)gr * ldc + gc] = v;
        }
    }
}

// Attention GEMM: computes lrelu(feat @ Wa + aW_b), dotted per-head against aA,
// accumulated straight into g_scores — the [E,H,D] tensor is never materialized.
__global__ void __launch_bounds__(256) gemm_attn(
    const float* __restrict__ A,       // g_feat, lda = CC
    const float* __restrict__ B,       // g_Wa + l*CC*HD, ldb = HD
    const float* __restrict__ bias,    // aW_b + l*HD
    const float* __restrict__ aA,      // aA_W + l*HD
    int M) {
    __shared__ float As[16][68];
    __shared__ float Bs[16][68];
    __shared__ float sred[64][17];
    const int tid = threadIdx.x;
    const int tx = tid & 15, ty = tid >> 4;
    const int row0 = blockIdx.y * 64, col0 = blockIdx.x * 64;
    float acc[4][4] = {};
    for (int k0 = 0; k0 < CC; k0 += 16) {
#pragma unroll
        for (int i = 0; i < 4; i++) {
            int t = tid + i * 256;
            int r = t >> 4, c = t & 15;
            int gr = row0 + r;
            As[c][r] = (gr < M) ? A[(size_t)gr * CC + k0 + c] : 0.0f;
        }
#pragma unroll
        for (int i = 0; i < 4; i++) {
            int t = tid + i * 256;
            int r = t >> 6, c = t & 63;
            Bs[r][c] = B[(size_t)(k0 + r) * HD + col0 + c];
        }
        __syncthreads();
#pragma unroll
        for (int kk = 0; kk < 16; kk++) {
            float4 a4 = *(const float4*)&As[kk][ty * 4];
            float4 b4 = *(const float4*)&Bs[kk][tx * 4];
            float a[4] = {a4.x, a4.y, a4.z, a4.w};
            float b[4] = {b4.x, b4.y, b4.z, b4.w};
#pragma unroll
            for (int i = 0; i < 4; i++)
#pragma unroll
                for (int j = 0; j < 4; j++)
                    acc[i][j] = fmaf(a[i], b[j], acc[i][j]);
        }
        __syncthreads();
    }
    const int head = col0 >> 7;   // 64-col tile lies fully within one head (D=128)
#pragma unroll
    for (int i = 0; i < 4; i++) {
        float p = 0.0f;
#pragma unroll
        for (int j = 0; j < 4; j++) {
            int gc = col0 + tx * 4 + j;
            float v = acc[i][j] + bias[gc];
            v = (v > 0.0f) ? v : 0.2f * v;
            p = fmaf(v, aA[gc], p);
        }
        sred[ty * 4 + i][tx] = p;
    }
    __syncthreads();
    if (tid < 64) {
        float s = 0.0f;
#pragma unroll
        for (int t = 0; t < 16; t++) s += sred[tid][t];
        int gr = row0 + tid;
        if (gr < M) atomicAdd(&g_scores[gr * HH + head], s);
    }
}

// ---------------- host ----------------
static inline void* sym(const void* s) {
    void* p = nullptr;
    cudaGetSymbolAddress(&p, s);
    return p;
}

extern "C" void kernel_launch(void* const* d_in, const int* in_sizes, int n_in,
                              void* d_out, int out_size) {
    const int*   seq      = (const int*)d_in[0];
    const int*   eidx     = (const int*)d_in[1];
    const float* dist     = (const float*)d_in[2];
    const float* seq_emb  = (const float*)d_in[3];
    const float* elW      = (const float*)d_in[4];
    const float* elb      = (const float*)d_in[5];
    const float* aW_W     = (const float*)d_in[6];
    const float* aW_b     = (const float*)d_in[7];
    const float* aA_W     = (const float*)d_in[8];
    const float* aA_b     = (const float*)d_in[9];
    const float* nW1 = (const float*)d_in[10]; const float* nb1 = (const float*)d_in[11];
    const float* nW2 = (const float*)d_in[12]; const float* nb2 = (const float*)d_in[13];
    const float* nW3 = (const float*)d_in[14]; const float* nb3 = (const float*)d_in[15];
    const float* dW1 = (const float*)d_in[16]; const float* db1 = (const float*)d_in[17];
    const float* dW2 = (const float*)d_in[18]; const float* db2 = (const float*)d_in[19];
    const float* eW1 = (const float*)d_in[20]; const float* eb1 = (const float*)d_in[21];
    const float* eW2 = (const float*)d_in[22]; const float* eb2 = (const float*)d_in[23];
    const float* eW3 = (const float*)d_in[24]; const float* eb3 = (const float*)d_in[25];
    const float* agW = (const float*)d_in[26]; const float* agb = (const float*)d_in[27];
    const float* n1g = (const float*)d_in[28]; const float* n1b = (const float*)d_in[29];
    const float* eg  = (const float*)d_in[30]; const float* eb  = (const float*)d_in[31];

    const int* srcp = eidx;
    const int* snkp = eidx + EE;

    float* feat   = (float*)sym(g_feat);
    float* t1     = (float*)sym(g_t1);
    float* t2     = (float*)sym(g_t2);
    float* nupd   = (float*)sym(g_nupd);
    float* agg    = (float*)sym(g_agg);
    float* nodes  = (float*)sym(g_nodes);
    float* upd    = (float*)sym(g_upd);
    float* dense  = (float*)sym(g_dense);
    float* dense2 = (float*)sym(g_dense2);
    float* Wa     = (float*)sym(g_Wa);
    float* eattr  = (float*)sym(g_eattr);

    // setup
    {
        int n = LL * HH * CC * DD;
        pack_wa<<<(n + 255) / 256, 256>>>(aW_W);
        node_embed<<<(NN * DD + 255) / 256, 256>>>(seq, seq_emb);
        edge_init<<<EE, 128>>>(dist, elW, elb);
    }

    for (int l = 0; l < LL; l++) {
        // feat = [nodes[src], nodes[snk], eattr]
        build_feat<<<(EE * 96 + 255) / 256, 256>>>(srcp, snkp);

        // attention scores (fused h + dot(aA))
        init_scores<<<(EE * HH + 255) / 256, 256>>>(aA_b + l * HH);
        gemm_attn<<<dim3(HD / 64, (EE + 63) / 64), 256>>>(
            feat, Wa + (size_t)l * CC * HD, aW_b + l * HD, aA_W + l * HD, EE);

        // node-update MLP on edges
        gemm_k<1><<<dim3(DD / 64, (EE + 63) / 64), 256>>>(feat, CC, nW1 + (size_t)l * CC * DD, DD,
                                                          nb1 + l * DD, t1, DD, EE, CC);
        gemm_k<1><<<dim3(DD / 64, (EE + 63) / 64), 256>>>(t1, DD, nW2 + (size_t)l * DD * DD, DD,
                                                          nb2 + l * DD, t2, DD, EE, DD);
        gemm_k<0><<<dim3(DD / 64, (EE + 63) / 64), 256>>>(t2, DD, nW3 + (size_t)l * DD * DD, DD,
                                                          nb3 + l * DD, nupd, DD, EE, DD);

        // scatter softmax over sink nodes
        smax_init<<<(NN * HH + 255) / 256, 256>>>();
        smax_atomic<<<(EE * HH + 255) / 256, 256>>>(snkp);
        att_kernel<<<(EE * HH + 255) / 256, 256>>>(snkp);
        norm_att<<<(EE * HH + 255) / 256, 256>>>(snkp);

        // aggregation
        zero_agg<<<(NN * HD + 255) / 256, 256>>>();
        aggregate<<<(EE * DD + 255) / 256, 256>>>(snkp);

        // node update + LN + dense MLP + LN (residual = upd both times, faithful to ref)
        gemm_k<0><<<dim3(DD / 64, (NN + 63) / 64), 256>>>(agg, HD, agW + (size_t)l * HD * DD, DD,
                                                          agb + l * DD, upd, DD, NN, HD);
        ln_kernel<<<NN, 128>>>(nodes, upd, n1g + l * DD, n1b + l * DD, nodes);
        gemm_k<1><<<dim3(D4 / 64, (NN + 63) / 64), 256>>>(nodes, DD, dW1 + (size_t)l * DD * D4, D4,
                                                          db1 + l * D4, dense, D4, NN, DD);
        gemm_k<0><<<dim3(DD / 64, (NN + 63) / 64), 256>>>(dense, D4, dW2 + (size_t)l * D4 * DD, DD,
                                                          db2 + l * DD, dense2, DD, NN, D4);
        ln_kernel<<<NN, 128>>>(dense2, upd, n1g + l * DD, n1b + l * DD, nodes);

        // edge MLP on refreshed feat
        build_feat<<<(EE * 96 + 255) / 256, 256>>>(srcp, snkp);
        gemm_k<1><<<dim3(DE / 64, (EE + 63) / 64), 256>>>(feat, CC, eW1 + (size_t)l * CC * DE, DE,
                                                          eb1 + l * DE, t1, DE, EE, CC);
        gemm_k<1><<<dim3(DE / 64, (EE + 63) / 64), 256>>>(t1, DE, eW2 + (size_t)l * DE * DE, DE,
                                                          eb2 + l * DE, t2, DE, EE, DE);
        gemm_k<0><<<dim3(DE / 64, (EE + 63) / 64), 256>>>(t2, DE, eW3 + (size_t)l * DE * DE, DE,
                                                          eb3 + l * DE, nupd, DE, EE, DE);
        ln_kernel<<<EE, 128>>>(eattr, nupd, eg + l * DE, eb + l * DE, eattr);
    }

    copy_out<<<(NN * DD + EE * DE + 255) / 256, 256>>>((float*)d_out);
}

// round 3
// speedup vs baseline: 1.9746x; 1.9746x over previous
#include <cuda_runtime.h>
#include <math.h>

#define NN 6000
#define EE 120000
#define DD 128
#define DE 128
#define HH 4
#define LL 2
#define CC 384      // 2*DD + DE
#define HD 512      // HH*DD
#define D4 512      // 4*DD

// ---------------- scratch (device globals; no allocation) ----------------
__device__ float    g_t1[(size_t)EE * DD];
__device__ float    g_t2[(size_t)EE * DD];
__device__ float    g_nupd[(size_t)EE * DD];     // nupd, later eu
__device__ float    g_eattr[(size_t)EE * DE];
__device__ float    g_scores[(size_t)EE * HH];
__device__ float    g_att[(size_t)EE * HH];
__device__ unsigned g_smaxu[NN * HH];
__device__ float    g_norm[NN * HH];
__device__ float    g_agg[(size_t)NN * HD];
__device__ float    g_nodes[NN * DD];
__device__ float    g_upd[NN * DD];
__device__ float    g_dense[(size_t)NN * D4];
__device__ float    g_dense2[NN * DD];
__device__ float    g_Wa[(size_t)LL * CC * HD];  // packed attention weights [l][c][h*D+d]

// ---------------- helpers ----------------
__device__ __forceinline__ float gelu_f(float x) {
    return 0.5f * x * (1.0f + erff(x * 0.70710678118654752440f));
}
__device__ __forceinline__ unsigned f2u(float f) {
    unsigned u = __float_as_uint(f);
    return (u & 0x80000000u) ? ~u : (u | 0x80000000u);
}
__device__ __forceinline__ float u2f(unsigned u) {
    return (u & 0x80000000u) ? __uint_as_float(u & 0x7fffffffu) : __uint_as_float(~u);
}
__device__ __forceinline__ unsigned tf32r(float x) {
    unsigned r;
    asm("cvt.rna.tf32.f32 %0, %1;" : "=r"(r) : "f"(x));
    return r;
}
__device__ __forceinline__ void mma_tf32(float* d, const unsigned* a, const unsigned* b) {
    asm volatile(
        "mma.sync.aligned.m16n8k8.row.col.f32.tf32.tf32.f32 "
        "{%0,%1,%2,%3}, {%4,%5,%6,%7}, {%8,%9}, {%0,%1,%2,%3};"
        : "+f"(d[0]), "+f"(d[1]), "+f"(d[2]), "+f"(d[3])
        : "r"(a[0]), "r"(a[1]), "r"(a[2]), "r"(a[3]), "r"(b[0]), "r"(b[1]));
}

// ---------------- small kernels ----------------
__global__ void pack_wa(const float* __restrict__ aW) {
    int i = blockIdx.x * blockDim.x + threadIdx.x;
    if (i >= LL * HH * CC * DD) return;
    int d = i % DD;
    int c = (i / DD) % CC;
    int h = (i / (DD * CC)) % HH;
    int l = i / (DD * CC * HH);
    g_Wa[((size_t)l * CC + c) * HD + h * DD + d] = aW[i];
}

__global__ void node_embed(const int* __restrict__ seq, const float* __restrict__ emb) {
    int i = blockIdx.x * blockDim.x + threadIdx.x;
    if (i < NN * DD) g_nodes[i] = emb[seq[i / DD] * DD + (i % DD)];
}

__global__ void edge_init(const float* __restrict__ dist,
                          const float* __restrict__ W, const float* __restrict__ b) {
    int e = blockIdx.x;
    int t = threadIdx.x;
    __shared__ float rbf[16];
    if (t < 16) {
        float mu = 2.0f + (20.0f / 15.0f) * (float)t;
        float z = (dist[e] - mu) * (1.0f / 1.25f);
        rbf[t] = expf(-z * z) + 1e-8f;
    }
    __syncthreads();
    float acc = b[t];
#pragma unroll
    for (int k = 0; k < 16; k++) acc = fmaf(rbf[k], W[k * DE + t], acc);
    g_eattr[(size_t)e * DE + t] = acc;
}

__global__ void init_scores(const float* __restrict__ aAb) {
    int i = blockIdx.x * blockDim.x + threadIdx.x;
    if (i < EE * HH) g_scores[i] = aAb[i % HH];
}

__global__ void smax_init() {
    int i = blockIdx.x * blockDim.x + threadIdx.x;
    if (i < NN * HH) { g_smaxu[i] = 0u; g_norm[i] = 0.0f; }
}

__global__ void smax_atomic(const int* __restrict__ snk) {
    int i = blockIdx.x * blockDim.x + threadIdx.x;
    if (i >= EE * HH) return;
    int e = i / HH, h = i % HH;
    atomicMax(&g_smaxu[snk[e] * HH + h], f2u(g_scores[i]));
}

__global__ void att_kernel(const int* __restrict__ snk) {
    int i = blockIdx.x * blockDim.x + threadIdx.x;
    if (i >= EE * HH) return;
    int e = i / HH, h = i % HH;
    int s = snk[e];
    float a = expf(g_scores[i] - u2f(g_smaxu[s * HH + h]));
    g_att[i] = a;
    atomicAdd(&g_norm[s * HH + h], a + 1e-12f);
}

__global__ void recip_norm() {
    int i = blockIdx.x * blockDim.x + threadIdx.x;
    if (i < NN * HH) g_norm[i] = 1.0f / g_norm[i];
}

__global__ void zero_agg() {
    int i = blockIdx.x * blockDim.x + threadIdx.x;
    if (i < NN * HD) g_agg[i] = 0.0f;
}

__global__ void aggregate(const int* __restrict__ snk) {
    int i = blockIdx.x * blockDim.x + threadIdx.x;   // over EE*DD
    if (i >= EE * DD) return;
    int e = i >> 7;
    int d = i & 127;
    float v = g_nupd[i];
    int s = snk[e];
    float4 w = *(const float4*)(g_att + e * 4);
    float4 rn = *(const float4*)(g_norm + s * 4);
    float* base = g_agg + (size_t)s * HD + d;
    atomicAdd(base,       w.x * rn.x * v);
    atomicAdd(base + 128, w.y * rn.y * v);
    atomicAdd(base + 256, w.z * rn.z * v);
    atomicAdd(base + 384, w.w * rn.w * v);
}

// LayerNorm over last dim (128). out = LN(A + R) * g + b.
__global__ void ln_kernel(const float* __restrict__ A, const float* __restrict__ R,
                          const float* __restrict__ g, const float* __restrict__ b,
                          float* __restrict__ out) {
    int r = blockIdx.x;
    int t = threadIdx.x;
    float x = A[(size_t)r * DD + t] + R[(size_t)r * DD + t];
    float s = x;
#pragma unroll
    for (int o = 16; o > 0; o >>= 1) s += __shfl_xor_sync(0xffffffffu, s, o);
    __shared__ float ws[4], ws2[4];
    if ((t & 31) == 0) ws[t >> 5] = s;
    __syncthreads();
    float mean = (ws[0] + ws[1] + ws[2] + ws[3]) * (1.0f / DD);
    float dx = x - mean;
    float v = dx * dx;
#pragma unroll
    for (int o = 16; o > 0; o >>= 1) v += __shfl_xor_sync(0xffffffffu, v, o);
    if ((t & 31) == 0) ws2[t >> 5] = v;
    __syncthreads();
    float var = (ws2[0] + ws2[1] + ws2[2] + ws2[3]) * (1.0f / DD);
    out[(size_t)r * DD + t] = dx * (1.0f / sqrtf(var + 1e-5f)) * g[t] + b[t];
}

__global__ void copy_out(float* __restrict__ out) {
    int i = blockIdx.x * blockDim.x + threadIdx.x;
    if (i < NN * DD) out[i] = g_nodes[i];
    else if (i < NN * DD + EE * DE) out[i] = g_eattr[i - NN * DD];
}

// ---------------- tf32 tensor-core GEMM ----------------
// C[M,N] = act(A[M,K] @ B[K,N] + bias). BM=128, BN=64, BK=16, 256 thr (8 warps),
// warp tile 32x32 (2 m16 x 4 n8 mma tiles). N multiple of 64, K multiple of 16.
// GATHER: A row r = [nodes[src[r]] | nodes[snk[r]] | eattr[r]], K=CC.
// ATTN:   fused lrelu + per-head dot(aA) reduced into g_scores (C never stored).
template <int ACT, bool GATHER, bool ATTN>   // ACT: 0 none, 1 gelu
__global__ void __launch_bounds__(256) gemm_tc(
    const float* __restrict__ A, int lda,
    const int* __restrict__ srcI, const int* __restrict__ snkI,
    const float* __restrict__ EATT,
    const float* __restrict__ B, int ldb,
    const float* __restrict__ bias,
    const float* __restrict__ aA,
    float* __restrict__ C, int ldc,
    int M, int K) {
    __shared__ float As[128][20];   // [m][k], stride 20 -> conflict-free frags
    __shared__ float Bs[16][72];    // [k][n], stride 72 -> conflict-free frags
    const int tid = threadIdx.x;
    const int row0 = blockIdx.y * 128, col0 = blockIdx.x * 64;
    const int wid = tid >> 5, lane = tid & 31, g = lane >> 2, tig = lane & 3;
    const int wm0 = (wid & 3) * 32, wn0 = (wid >> 2) * 32;

    int arow[2], agrow[2], asrc[2], asnk[2];
#pragma unroll
    for (int i = 0; i < 2; i++) {
        int idx = tid + i * 256;
        arow[i] = idx >> 2;
        int gr = row0 + arow[i];
        if (gr > M - 1) gr = M - 1;
        agrow[i] = gr;
        if (GATHER) { asrc[i] = srcI[gr]; asnk[i] = snkI[gr]; }
    }
    const int acol = (tid & 3) * 4;
    const int brow = tid >> 4, bcol = (tid & 15) * 4;

    float acc[2][4][4];
#pragma unroll
    for (int mt = 0; mt < 2; mt++)
#pragma unroll
        for (int nt = 0; nt < 4; nt++)
#pragma unroll
            for (int q = 0; q < 4; q++) acc[mt][nt][q] = 0.0f;

    for (int k0 = 0; k0 < K; k0 += 16) {
#pragma unroll
        for (int i = 0; i < 2; i++) {
            int kk = k0 + acol;
            const float* p;
            if (GATHER) {
                if (kk < 128)      p = A + (size_t)asrc[i] * DD + kk;
                else if (kk < 256) p = A + (size_t)asnk[i] * DD + (kk - 128);
                else               p = EATT + (size_t)agrow[i] * DE + (kk - 256);
            } else {
                p = A + (size_t)agrow[i] * lda + kk;
            }
            float4 v = *(const float4*)p;
            As[arow[i]][acol + 0] = __uint_as_float(tf32r(v.x));
            As[arow[i]][acol + 1] = __uint_as_float(tf32r(v.y));
            As[arow[i]][acol + 2] = __uint_as_float(tf32r(v.z));
            As[arow[i]][acol + 3] = __uint_as_float(tf32r(v.w));
        }
        {
            float4 v = *(const float4*)(B + (size_t)(k0 + brow) * ldb + col0 + bcol);
            Bs[brow][bcol + 0] = __uint_as_float(tf32r(v.x));
            Bs[brow][bcol + 1] = __uint_as_float(tf32r(v.y));
            Bs[brow][bcol + 2] = __uint_as_float(tf32r(v.z));
            Bs[brow][bcol + 3] = __uint_as_float(tf32r(v.w));
        }
        __syncthreads();
#pragma unroll
        for (int kk = 0; kk < 16; kk += 8) {
            unsigned af[2][4], bf[4][2];
#pragma unroll
            for (int mt = 0; mt < 2; mt++) {
                int r = wm0 + mt * 16 + g;
                af[mt][0] = __float_as_uint(As[r][kk + tig]);
                af[mt][1] = __float_as_uint(As[r + 8][kk + tig]);
                af[mt][2] = __float_as_uint(As[r][kk + tig + 4]);
                af[mt][3] = __float_as_uint(As[r + 8][kk + tig + 4]);
            }
#pragma unroll
            for (int nt = 0; nt < 4; nt++) {
                int c = wn0 + nt * 8 + g;
                bf[nt][0] = __float_as_uint(Bs[kk + tig][c]);
                bf[nt][1] = __float_as_uint(Bs[kk + tig + 4][c]);
            }
#pragma unroll
            for (int mt = 0; mt < 2; mt++)
#pragma unroll
                for (int nt = 0; nt < 4; nt++)
                    mma_tf32(acc[mt][nt], af[mt], bf[nt]);
        }
        __syncthreads();
    }

    if (ATTN) {
        const int head = (col0 + wn0) >> 7;
#pragma unroll
        for (int mt = 0; mt < 2; mt++) {
#pragma unroll
            for (int i2 = 0; i2 < 2; i2++) {
                int gr = row0 + wm0 + mt * 16 + g + i2 * 8;
                float p = 0.0f;
#pragma unroll
                for (int nt = 0; nt < 4; nt++) {
#pragma unroll
                    for (int j = 0; j < 2; j++) {
                        int gc = col0 + wn0 + nt * 8 + 2 * tig + j;
                        float v = acc[mt][nt][i2 * 2 + j] + bias[gc];
                        v = (v > 0.0f) ? v : 0.2f * v;
                        p = fmaf(v, aA[gc], p);
                    }
                }
                p += __shfl_xor_sync(0xffffffffu, p, 1);
                p += __shfl_xor_sync(0xffffffffu, p, 2);
                if (tig == 0 && gr < M) atomicAdd(&g_scores[gr * HH + head], p);
            }
        }
    } else {
#pragma unroll
        for (int mt = 0; mt < 2; mt++) {
#pragma unroll
            for (int i2 = 0; i2 < 2; i2++) {
                int gr = row0 + wm0 + mt * 16 + g + i2 * 8;
                if (gr >= M) continue;
#pragma unroll
                for (int nt = 0; nt < 4; nt++) {
                    int gc = col0 + wn0 + nt * 8 + 2 * tig;
                    float v0 = acc[mt][nt][i2 * 2 + 0] + bias[gc];
                    float v1 = acc[mt][nt][i2 * 2 + 1] + bias[gc + 1];
                    if (ACT == 1) { v0 = gelu_f(v0); v1 = gelu_f(v1); }
                    *(float2*)&C[(size_t)gr * ldc + gc] = make_float2(v0, v1);
                }
            }
        }
    }
}

// ---------------- host ----------------
static inline void* sym(const void* s) {
    void* p = nullptr;
    cudaGetSymbolAddress(&p, s);
    return p;
}

extern "C" void kernel_launch(void* const* d_in, const int* in_sizes, int n_in,
                              void* d_out, int out_size) {
    const int*   seq      = (const int*)d_in[0];
    const int*   eidx     = (const int*)d_in[1];
    const float* dist     = (const float*)d_in[2];
    const float* seq_emb  = (const float*)d_in[3];
    const float* elW      = (const float*)d_in[4];
    const float* elb      = (const float*)d_in[5];
    const float* aW_W     = (const float*)d_in[6];
    const float* aW_b     = (const float*)d_in[7];
    const float* aA_W     = (const float*)d_in[8];
    const float* aA_b     = (const float*)d_in[9];
    const float* nW1 = (const float*)d_in[10]; const float* nb1 = (const float*)d_in[11];
    const float* nW2 = (const float*)d_in[12]; const float* nb2 = (const float*)d_in[13];
    const float* nW3 = (const float*)d_in[14]; const float* nb3 = (const float*)d_in[15];
    const float* dW1 = (const float*)d_in[16]; const float* db1 = (const float*)d_in[17];
    const float* dW2 = (const float*)d_in[18]; const float* db2 = (const float*)d_in[19];
    const float* eW1 = (const float*)d_in[20]; const float* eb1 = (const float*)d_in[21];
    const float* eW2 = (const float*)d_in[22]; const float* eb2 = (const float*)d_in[23];
    const float* eW3 = (const float*)d_in[24]; const float* eb3 = (const float*)d_in[25];
    const float* agW = (const float*)d_in[26]; const float* agb = (const float*)d_in[27];
    const float* n1g = (const float*)d_in[28]; const float* n1b = (const float*)d_in[29];
    const float* eg  = (const float*)d_in[30]; const float* eb  = (const float*)d_in[31];

    const int* srcp = eidx;
    const int* snkp = eidx + EE;

    float* t1     = (float*)sym(g_t1);
    float* t2     = (float*)sym(g_t2);
    float* nupd   = (float*)sym(g_nupd);
    float* agg    = (float*)sym(g_agg);
    float* nodes  = (float*)sym(g_nodes);
    float* upd    = (float*)sym(g_upd);
    float* dense  = (float*)sym(g_dense);
    float* dense2 = (float*)sym(g_dense2);
    float* Wa     = (float*)sym(g_Wa);
    float* eattr  = (float*)sym(g_eattr);

    const dim3 gE1(2, (EE + 127) / 128);    // edge GEMMs, N=128
    const dim3 gEA(8, (EE + 127) / 128);    // attention GEMM, N=512
    const dim3 gN1(2, (NN + 127) / 128);    // node GEMMs, N=128
    const dim3 gN4(8, (NN + 127) / 128);    // dense MLP up, N=512

    {
        int n = LL * HH * CC * DD;
        pack_wa<<<(n + 255) / 256, 256>>>(aW_W);
        node_embed<<<(NN * DD + 255) / 256, 256>>>(seq, seq_emb);
        edge_init<<<EE, 128>>>(dist, elW, elb);
    }

    for (int l = 0; l < LL; l++) {
        // attention scores (gathered feat, fused lrelu + dot(aA))
        init_scores<<<(EE * HH + 255) / 256, 256>>>(aA_b + l * HH);
        gemm_tc<0, true, true><<<gEA, 256>>>(
            nodes, 0, srcp, snkp, eattr,
            Wa + (size_t)l * CC * HD, HD, aW_b + l * HD, aA_W + l * HD,
            nullptr, 0, EE, CC);

        // node-update MLP on edges (first GEMM gathers feat)
        gemm_tc<1, true, false><<<gE1, 256>>>(nodes, 0, srcp, snkp, eattr,
            nW1 + (size_t)l * CC * DD, DD, nb1 + l * DD, nullptr, t1, DD, EE, CC);
        gemm_tc<1, false, false><<<gE1, 256>>>(t1, DD, nullptr, nullptr, nullptr,
            nW2 + (size_t)l * DD * DD, DD, nb2 + l * DD, nullptr, t2, DD, EE, DD);
        gemm_tc<0, false, false><<<gE1, 256>>>(t2, DD, nullptr, nullptr, nullptr,
            nW3 + (size_t)l * DD * DD, DD, nb3 + l * DD, nullptr, nupd, DD, EE, DD);

        // scatter softmax over sink nodes
        smax_init<<<(NN * HH + 255) / 256, 256>>>();
        smax_atomic<<<(EE * HH + 255) / 256, 256>>>(snkp);
        att_kernel<<<(EE * HH + 255) / 256, 256>>>(snkp);
        recip_norm<<<(NN * HH + 255) / 256, 256>>>();

        // aggregation
        zero_agg<<<(NN * HD + 255) / 256, 256>>>();
        aggregate<<<(EE * DD + 255) / 256, 256>>>(snkp);

        // node update + LN + dense MLP + LN
        gemm_tc<0, false, false><<<gN1, 256>>>(agg, HD, nullptr, nullptr, nullptr,
            agW + (size_t)l * HD * DD, DD, agb + l * DD, nullptr, upd, DD, NN, HD);
        ln_kernel<<<NN, 128>>>(nodes, upd, n1g + l * DD, n1b + l * DD, nodes);
        gemm_tc<1, false, false><<<gN4, 256>>>(nodes, DD, nullptr, nullptr, nullptr,
            dW1 + (size_t)l * DD * D4, D4, db1 + l * D4, nullptr, dense, D4, NN, DD);
        gemm_tc<0, false, false><<<gN1, 256>>>(dense, D4, nullptr, nullptr, nullptr,
            dW2 + (size_t)l * D4 * DD, DD, db2 + l * DD, nullptr, dense2, DD, NN, D4);
        ln_kernel<<<NN, 128>>>(dense2, upd, n1g + l * DD, n1b + l * DD, nodes);

        // edge MLP (first GEMM gathers refreshed feat)
        gemm_tc<1, true, false><<<gE1, 256>>>(nodes, 0, srcp, snkp, eattr,
            eW1 + (size_t)l * CC * DE, DE, eb1 + l * DE, nullptr, t1, DE, EE, CC);
        gemm_tc<1, false, false><<<gE1, 256>>>(t1, DE, nullptr, nullptr, nullptr,
            eW2 + (size_t)l * DE * DE, DE, eb2 + l * DE, nullptr, t2, DE, EE, DE);
        gemm_tc<0, false, false><<<gE1, 256>>>(t2, DE, nullptr, nullptr, nullptr,
            eW3 + (size_t)l * DE * DE, DE, eb3 + l * DE, nullptr, nupd, DE, EE, DE);
        ln_kernel<<<EE, 128>>>(eattr, nupd, eg + l * DE, eb + l * DE, eattr);
    }

    copy_out<<<(NN * DD + EE * DE + 255) / 256, 256>>>((float*)d_out);
}

// round 4
// speedup vs baseline: 2.3284x; 1.1792x over previous
#include <cuda_runtime.h>
#include <math.h>

#define NN 6000
#define EE 120000
#define DD 128
#define DE 128
#define HH 4
#define LL 2
#define CC 384      // 2*DD + DE
#define HD 512      // HH*DD
#define D4 512      // 4*DD

// ---------------- scratch (device globals; no allocation) ----------------
__device__ float    g_t1[(size_t)EE * DD];
__device__ float    g_t2[(size_t)EE * DD];
__device__ float    g_nupd[(size_t)EE * DD];
__device__ float    g_eattr[(size_t)EE * DE];
__device__ float    g_scores[(size_t)EE * HH];
__device__ float    g_att[(size_t)EE * HH];
__device__ unsigned g_smaxu[NN * HH];
__device__ float    g_norm[NN * HH];
__device__ float    g_agg[(size_t)NN * HD];
__device__ float    g_nodes[NN * DD];
__device__ float    g_upd[NN * DD];
__device__ float    g_dense[(size_t)NN * D4];
__device__ float    g_dense2[NN * DD];
__device__ float    g_Wa[(size_t)LL * CC * HD];

// ---------------- helpers ----------------
__device__ __forceinline__ float gelu_f(float x) {
    return 0.5f * x * (1.0f + erff(x * 0.70710678118654752440f));
}
__device__ __forceinline__ unsigned f2u(float f) {
    unsigned u = __float_as_uint(f);
    return (u & 0x80000000u) ? ~u : (u | 0x80000000u);
}
__device__ __forceinline__ float u2f(unsigned u) {
    return (u & 0x80000000u) ? __uint_as_float(u & 0x7fffffffu) : __uint_as_float(~u);
}
__device__ __forceinline__ float tf32f(float x) {
    unsigned r;
    asm("cvt.rna.tf32.f32 %0, %1;" : "=r"(r) : "f"(x));
    return __uint_as_float(r);
}
__device__ __forceinline__ float4 tf32f4(float4 v) {
    return make_float4(tf32f(v.x), tf32f(v.y), tf32f(v.z), tf32f(v.w));
}
__device__ __forceinline__ void mma_tf32(float* d, const unsigned* a, const unsigned* b) {
    asm volatile(
        "mma.sync.aligned.m16n8k8.row.col.f32.tf32.tf32.f32 "
        "{%0,%1,%2,%3}, {%4,%5,%6,%7}, {%8,%9}, {%0,%1,%2,%3};"
        : "+f"(d[0]), "+f"(d[1]), "+f"(d[2]), "+f"(d[3])
        : "r"(a[0]), "r"(a[1]), "r"(a[2]), "r"(a[3]), "r"(b[0]), "r"(b[1]));
}

// ---------------- small kernels ----------------
__global__ void pack_wa(const float* __restrict__ aW) {
    int i = blockIdx.x * blockDim.x + threadIdx.x;
    if (i >= LL * HH * CC * DD) return;
    int d = i % DD;
    int c = (i / DD) % CC;
    int h = (i / (DD * CC)) % HH;
    int l = i / (DD * CC * HH);
    g_Wa[((size_t)l * CC + c) * HD + h * DD + d] = aW[i];
}

__global__ void node_embed(const int* __restrict__ seq, const float* __restrict__ emb) {
    int i = blockIdx.x * blockDim.x + threadIdx.x;
    if (i < NN * DD) g_nodes[i] = emb[seq[i / DD] * DD + (i % DD)];
}

__global__ void edge_init(const float* __restrict__ dist,
                          const float* __restrict__ W, const float* __restrict__ b) {
    int e = blockIdx.x;
    int t = threadIdx.x;
    __shared__ float rbf[16];
    if (t < 16) {
        float mu = 2.0f + (20.0f / 15.0f) * (float)t;
        float z = (dist[e] - mu) * (1.0f / 1.25f);
        rbf[t] = expf(-z * z) + 1e-8f;
    }
    __syncthreads();
    float acc = b[t];
#pragma unroll
    for (int k = 0; k < 16; k++) acc = fmaf(rbf[k], W[k * DE + t], acc);
    g_eattr[(size_t)e * DE + t] = acc;
}

__global__ void smax_init() {
    int i = blockIdx.x * blockDim.x + threadIdx.x;
    if (i < NN * HH) { g_smaxu[i] = 0u; g_norm[i] = 0.0f; }
}

__global__ void smax_atomic(const int* __restrict__ snk) {
    int i = blockIdx.x * blockDim.x + threadIdx.x;
    if (i >= EE * HH) return;
    int e = i / HH, h = i % HH;
    atomicMax(&g_smaxu[snk[e] * HH + h], f2u(g_scores[i]));
}

__global__ void att_kernel(const int* __restrict__ snk) {
    int i = blockIdx.x * blockDim.x + threadIdx.x;
    if (i >= EE * HH) return;
    int e = i / HH, h = i % HH;
    int s = snk[e];
    float a = expf(g_scores[i] - u2f(g_smaxu[s * HH + h]));
    g_att[i] = a;
    atomicAdd(&g_norm[s * HH + h], a + 1e-12f);
}

__global__ void recip_norm() {
    int i = blockIdx.x * blockDim.x + threadIdx.x;
    if (i < NN * HH) g_norm[i] = 1.0f / g_norm[i];
}

__global__ void zero_agg() {
    int i = blockIdx.x * blockDim.x + threadIdx.x;
    if (i < NN * HD) g_agg[i] = 0.0f;
}

__global__ void aggregate(const int* __restrict__ snk) {
    int i = blockIdx.x * blockDim.x + threadIdx.x;   // over EE*32 (float4 lanes)
    if (i >= EE * 32) return;
    int e = i >> 5;
    int d4 = i & 31;
    float4 v = ((const float4*)g_nupd)[(size_t)e * 32 + d4];
    int s = snk[e];
    float4 w = *(const float4*)(g_att + e * 4);
    float4 rn = *(const float4*)(g_norm + s * 4);
    float4* base = (float4*)(g_agg + (size_t)s * HD) + d4;
    float c0 = w.x * rn.x, c1 = w.y * rn.y, c2 = w.z * rn.z, c3 = w.w * rn.w;
    atomicAdd(base,      make_float4(c0 * v.x, c0 * v.y, c0 * v.z, c0 * v.w));
    atomicAdd(base + 32, make_float4(c1 * v.x, c1 * v.y, c1 * v.z, c1 * v.w));
    atomicAdd(base + 64, make_float4(c2 * v.x, c2 * v.y, c2 * v.z, c2 * v.w));
    atomicAdd(base + 96, make_float4(c3 * v.x, c3 * v.y, c3 * v.z, c3 * v.w));
}

// LayerNorm over last dim (128). out = LN(A + R) * g + b.
__global__ void ln_kernel(const float* __restrict__ A, const float* __restrict__ R,
                          const float* __restrict__ g, const float* __restrict__ b,
                          float* __restrict__ out) {
    int r = blockIdx.x;
    int t = threadIdx.x;
    float x = A[(size_t)r * DD + t] + R[(size_t)r * DD + t];
    float s = x;
#pragma unroll
    for (int o = 16; o > 0; o >>= 1) s += __shfl_xor_sync(0xffffffffu, s, o);
    __shared__ float ws[4], ws2[4];
    if ((t & 31) == 0) ws[t >> 5] = s;
    __syncthreads();
    float mean = (ws[0] + ws[1] + ws[2] + ws[3]) * (1.0f / DD);
    float dx = x - mean;
    float v = dx * dx;
#pragma unroll
    for (int o = 16; o > 0; o >>= 1) v += __shfl_xor_sync(0xffffffffu, v, o);
    if ((t & 31) == 0) ws2[t >> 5] = v;
    __syncthreads();
    float var = (ws2[0] + ws2[1] + ws2[2] + ws2[3]) * (1.0f / DD);
    out[(size_t)r * DD + t] = dx * (1.0f / sqrtf(var + 1e-5f)) * g[t] + b[t];
}

__global__ void copy_out(float* __restrict__ out) {
    int i = blockIdx.x * blockDim.x + threadIdx.x;
    if (i < NN * DD) out[i] = g_nodes[i];
    else if (i < NN * DD + EE * DE) out[i] = g_eattr[i - NN * DD];
}

// ---------------- tf32 tensor-core GEMM ----------------
// C[M,N] = act(A[M,K] @ B[K,N] + bias). BM=128, BN=128, BK=16, 256 thr (8 warps),
// warp tile 64x32 (4 m16 x 4 n8). N multiple of 128, K multiple of 16.
// GATHER: A row r = [nodes[src[r]] | nodes[snk[r]] | eattr[r]], K=CC.
// ATTN:   BN==head size; fused lrelu + dot(aA); scores written directly.
template <int ACT, bool GATHER, bool ATTN>   // ACT: 0 none, 1 gelu
__global__ void __launch_bounds__(256) gemm_tc(
    const float* __restrict__ A, int lda,
    const int* __restrict__ srcI, const int* __restrict__ snkI,
    const float* __restrict__ EATT,
    const float* __restrict__ B, int ldb,
    const float* __restrict__ bias,
    const float* __restrict__ aA, const float* __restrict__ aAb,
    float* __restrict__ C, int ldc,
    int M, int K) {
    __shared__ float As[128][20];    // stride 20 -> conflict-free frag loads
    __shared__ float Bs[16][136];    // stride 136 -> conflict-free frag loads
    __shared__ float sred[128][5];
    const int tid = threadIdx.x;
    const int row0 = blockIdx.y * 128, col0 = blockIdx.x * 128;
    const int wid = tid >> 5, lane = tid & 31, g = lane >> 2, tig = lane & 3;
    const int wm = wid >> 2, wn = wid & 3;
    const int wm0 = wm * 64, wn0 = wn * 32;

    // A-load addressing: rows tid>>2 and +64, cols (tid&3)*4
    int arow = tid >> 2;
    const int acol = (tid & 3) * 4;
    int agrow[2], asrc[2], asnk[2];
#pragma unroll
    for (int i = 0; i < 2; i++) {
        int gr = row0 + arow + i * 64;
        if (gr > M - 1) gr = M - 1;
        agrow[i] = gr;
        if (GATHER) { asrc[i] = srcI[gr]; asnk[i] = snkI[gr]; }
    }
    // B-load addressing: rows tid>>5 and +8, cols (tid&31)*4
    const int brow = tid >> 5, bcol = (tid & 31) * 4;

    float acc[4][4][4];
#pragma unroll
    for (int mt = 0; mt < 4; mt++)
#pragma unroll
        for (int nt = 0; nt < 4; nt++)
#pragma unroll
            for (int q = 0; q < 4; q++) acc[mt][nt][q] = 0.0f;

    for (int k0 = 0; k0 < K; k0 += 16) {
        int kk = k0 + acol;
#pragma unroll
        for (int i = 0; i < 2; i++) {
            const float* p;
            if (GATHER) {
                if (kk < 128)      p = A + (size_t)asrc[i] * DD + kk;
                else if (kk < 256) p = A + (size_t)asnk[i] * DD + (kk - 128);
                else               p = EATT + (size_t)agrow[i] * DE + (kk - 256);
            } else {
                p = A + (size_t)agrow[i] * lda + kk;
            }
            *(float4*)&As[arow + i * 64][acol] = tf32f4(*(const float4*)p);
        }
#pragma unroll
        for (int i = 0; i < 2; i++) {
            float4 v = *(const float4*)(B + (size_t)(k0 + brow + i * 8) * ldb + col0 + bcol);
            *(float4*)&Bs[brow + i * 8][bcol] = tf32f4(v);
        }
        __syncthreads();
#pragma unroll
        for (int ks = 0; ks < 16; ks += 8) {
            unsigned af[4][4], bf[4][2];
#pragma unroll
            for (int mt = 0; mt < 4; mt++) {
                int r = wm0 + mt * 16 + g;
                af[mt][0] = __float_as_uint(As[r][ks + tig]);
                af[mt][1] = __float_as_uint(As[r + 8][ks + tig]);
                af[mt][2] = __float_as_uint(As[r][ks + tig + 4]);
                af[mt][3] = __float_as_uint(As[r + 8][ks + tig + 4]);
            }
#pragma unroll
            for (int nt = 0; nt < 4; nt++) {
                int c = wn0 + nt * 8 + g;
                bf[nt][0] = __float_as_uint(Bs[ks + tig][c]);
                bf[nt][1] = __float_as_uint(Bs[ks + tig + 4][c]);
            }
#pragma unroll
            for (int mt = 0; mt < 4; mt++)
#pragma unroll
                for (int nt = 0; nt < 4; nt++)
                    mma_tf32(acc[mt][nt], af[mt], bf[nt]);
        }
        __syncthreads();
    }

    if (ATTN) {
        const int head = col0 >> 7;   // BN==128==head width
#pragma unroll
        for (int mt = 0; mt < 4; mt++) {
#pragma unroll
            for (int i2 = 0; i2 < 2; i2++) {
                int rl = wm0 + mt * 16 + i2 * 8 + g;
                float p = 0.0f;
#pragma unroll
                for (int nt = 0; nt < 4; nt++) {
#pragma unroll
                    for (int j = 0; j < 2; j++) {
                        int gc = col0 + wn0 + nt * 8 + 2 * tig + j;
                        float v = acc[mt][nt][i2 * 2 + j] + bias[gc];
                        v = (v > 0.0f) ? v : 0.2f * v;
                        p = fmaf(v, aA[gc], p);
                    }
                }
                p += __shfl_xor_sync(0xffffffffu, p, 1);
                p += __shfl_xor_sync(0xffffffffu, p, 2);
                if (tig == 0) sred[rl][wn] = p;
            }
        }
        __syncthreads();
        if (tid < 128) {
            int gr = row0 + tid;
            if (gr < M) {
                float s = sred[tid][0] + sred[tid][1] + sred[tid][2] + sred[tid][3] + aAb[head];
                g_scores[gr * HH + head] = s;
            }
        }
    } else {
#pragma unroll
        for (int mt = 0; mt < 4; mt++) {
#pragma unroll
            for (int i2 = 0; i2 < 2; i2++) {
                int gr = row0 + wm0 + mt * 16 + i2 * 8 + g;
                if (gr >= M) continue;
#pragma unroll
                for (int nt = 0; nt < 4; nt++) {
                    int gc = col0 + wn0 + nt * 8 + 2 * tig;
                    float v0 = acc[mt][nt][i2 * 2 + 0] + bias[gc];
                    float v1 = acc[mt][nt][i2 * 2 + 1] + bias[gc + 1];
                    if (ACT == 1) { v0 = gelu_f(v0); v1 = gelu_f(v1); }
                    *(float2*)&C[(size_t)gr * ldc + gc] = make_float2(v0, v1);
                }
            }
        }
    }
}

// ---------------- host ----------------
static inline void* sym(const void* s) {
    void* p = nullptr;
    cudaGetSymbolAddress(&p, s);
    return p;
}

extern "C" void kernel_launch(void* const* d_in, const int* in_sizes, int n_in,
                              void* d_out, int out_size) {
    const int*   seq      = (const int*)d_in[0];
    const int*   eidx     = (const int*)d_in[1];
    const float* dist     = (const float*)d_in[2];
    const float* seq_emb  = (const float*)d_in[3];
    const float* elW      = (const float*)d_in[4];
    const float* elb      = (const float*)d_in[5];
    const float* aW_W     = (const float*)d_in[6];
    const float* aW_b     = (const float*)d_in[7];
    const float* aA_W     = (const float*)d_in[8];
    const float* aA_b     = (const float*)d_in[9];
    const float* nW1 = (const float*)d_in[10]; const float* nb1 = (const float*)d_in[11];
    const float* nW2 = (const float*)d_in[12]; const float* nb2 = (const float*)d_in[13];
    const float* nW3 = (const float*)d_in[14]; const float* nb3 = (const float*)d_in[15];
    const float* dW1 = (const float*)d_in[16]; const float* db1 = (const float*)d_in[17];
    const float* dW2 = (const float*)d_in[18]; const float* db2 = (const float*)d_in[19];
    const float* eW1 = (const float*)d_in[20]; const float* eb1 = (const float*)d_in[21];
    const float* eW2 = (const float*)d_in[22]; const float* eb2 = (const float*)d_in[23];
    const float* eW3 = (const float*)d_in[24]; const float* eb3 = (const float*)d_in[25];
    const float* agW = (const float*)d_in[26]; const float* agb = (const float*)d_in[27];
    const float* n1g = (const float*)d_in[28]; const float* n1b = (const float*)d_in[29];
    const float* eg  = (const float*)d_in[30]; const float* eb  = (const float*)d_in[31];

    const int* srcp = eidx;
    const int* snkp = eidx + EE;

    float* t1     = (float*)sym(g_t1);
    float* t2     = (float*)sym(g_t2);
    float* nupd   = (float*)sym(g_nupd);
    float* agg    = (float*)sym(g_agg);
    float* nodes  = (float*)sym(g_nodes);
    float* upd    = (float*)sym(g_upd);
    float* dense  = (float*)sym(g_dense);
    float* dense2 = (float*)sym(g_dense2);
    float* Wa     = (float*)sym(g_Wa);
    float* eattr  = (float*)sym(g_eattr);

    const int GME = (EE + 127) / 128;
    const int GMN = (NN + 127) / 128;
    const dim3 gE1(1, GME);    // edge GEMMs, N=128
    const dim3 gEA(4, GME);    // attention GEMM, N=512 (one head per block col)
    const dim3 gN1(1, GMN);    // node GEMMs, N=128
    const dim3 gN4(4, GMN);    // dense MLP up, N=512

    {
        int n = LL * HH * CC * DD;
        pack_wa<<<(n + 255) / 256, 256>>>(aW_W);
        node_embed<<<(NN * DD + 255) / 256, 256>>>(seq, seq_emb);
        edge_init<<<EE, 128>>>(dist, elW, elb);
    }

    for (int l = 0; l < LL; l++) {
        // attention scores (gathered feat, fused lrelu + dot(aA), direct store)
        gemm_tc<0, true, true><<<gEA, 256>>>(
            nodes, 0, srcp, snkp, eattr,
            Wa + (size_t)l * CC * HD, HD, aW_b + l * HD, aA_W + l * HD, aA_b + l * HH,
            nullptr, 0, EE, CC);

        // node-update MLP on edges (first GEMM gathers feat)
        gemm_tc<1, true, false><<<gE1, 256>>>(nodes, 0, srcp, snkp, eattr,
            nW1 + (size_t)l * CC * DD, DD, nb1 + l * DD, nullptr, nullptr, t1, DD, EE, CC);
        gemm_tc<1, false, false><<<gE1, 256>>>(t1, DD, nullptr, nullptr, nullptr,
            nW2 + (size_t)l * DD * DD, DD, nb2 + l * DD, nullptr, nullptr, t2, DD, EE, DD);
        gemm_tc<0, false, false><<<gE1, 256>>>(t2, DD, nullptr, nullptr, nullptr,
            nW3 + (size_t)l * DD * DD, DD, nb3 + l * DD, nullptr, nullptr, nupd, DD, EE, DD);

        // scatter softmax over sink nodes
        smax_init<<<(NN * HH + 255) / 256, 256>>>();
        smax_atomic<<<(EE * HH + 255) / 256, 256>>>(snkp);
        att_kernel<<<(EE * HH + 255) / 256, 256>>>(snkp);
        recip_norm<<<(NN * HH + 255) / 256, 256>>>();

        // aggregation (float4 atomics)
        zero_agg<<<(NN * HD + 255) / 256, 256>>>();
        aggregate<<<(EE * 32 + 255) / 256, 256>>>(snkp);

        // node update + LN + dense MLP + LN
        gemm_tc<0, false, false><<<gN1, 256>>>(agg, HD, nullptr, nullptr, nullptr,
            agW + (size_t)l * HD * DD, DD, agb + l * DD, nullptr, nullptr, upd, DD, NN, HD);
        ln_kernel<<<NN, 128>>>(nodes, upd, n1g + l * DD, n1b + l * DD, nodes);
        gemm_tc<1, false, false><<<gN4, 256>>>(nodes, DD, nullptr, nullptr, nullptr,
            dW1 + (size_t)l * DD * D4, D4, db1 + l * D4, nullptr, nullptr, dense, D4, NN, DD);
        gemm_tc<0, false, false><<<gN1, 256>>>(dense, D4, nullptr, nullptr, nullptr,
            dW2 + (size_t)l * D4 * DD, DD, db2 + l * DD, nullptr, nullptr, dense2, DD, NN, D4);
        ln_kernel<<<NN, 128>>>(dense2, upd, n1g + l * DD, n1b + l * DD, nodes);

        // edge MLP (first GEMM gathers refreshed feat)
        gemm_tc<1, true, false><<<gE1, 256>>>(nodes, 0, srcp, snkp, eattr,
            eW1 + (size_t)l * CC * DE, DE, eb1 + l * DE, nullptr, nullptr, t1, DE, EE, CC);
        gemm_tc<1, false, false><<<gE1, 256>>>(t1, DE, nullptr, nullptr, nullptr,
            eW2 + (size_t)l * DE * DE, DE, eb2 + l * DE, nullptr, nullptr, t2, DE, EE, DE);
        gemm_tc<0, false, false><<<gE1, 256>>>(t2, DE, nullptr, nullptr, nullptr,
            eW3 + (size_t)l * DE * DE, DE, eb3 + l * DE, nullptr, nullptr, nupd, DE, EE, DE);
        ln_kernel<<<EE, 128>>>(eattr, nupd, eg + l * DE, eb + l * DE, eattr);
    }

    copy_out<<<(NN * DD + EE * DE + 255) / 256, 256>>>((float*)d_out);
}

// round 5
// speedup vs baseline: 3.4086x; 1.4640x over previous
#include <cuda_runtime.h>
#include <math.h>

#define NN 6000
#define EE 120000
#define DD 128
#define DE 128
#define HH 4
#define LL 2
#define CC 384      // 2*DD + DE
#define HD 512      // HH*DD
#define D4 512      // 4*DD

// ---------------- scratch (device globals; no allocation) ----------------
__device__ float    g_t1[(size_t)EE * DD];
__device__ float    g_t2[(size_t)EE * DD];
__device__ float    g_nupd[(size_t)EE * DD];
__device__ float    g_eattr[(size_t)EE * DE];
__device__ float    g_scores[(size_t)EE * HH];
__device__ float    g_att[(size_t)EE * HH];
__device__ unsigned g_smaxu[NN * HH];
__device__ float    g_norm[NN * HH];
__device__ float    g_agg[(size_t)NN * HD];
__device__ float    g_nodes[NN * DD];
__device__ float    g_upd[NN * DD];
__device__ float    g_dense[(size_t)NN * D4];
__device__ float    g_dense2[NN * DD];
__device__ float    g_Wa[(size_t)LL * CC * HD];    // attention W packed [l][c][h*D+d]
__device__ float    g_WU1[(size_t)LL * DD * 1280]; // [Wa_src|Wa_snk|nW1_src|nW1_snk]
__device__ float    g_WU2[(size_t)LL * DD * 256];  // [eW1_src|eW1_snk]
__device__ float    g_U1[(size_t)NN * 1280];       // per-node partials (attn + nmlp1)
__device__ float    g_U2[(size_t)NN * 256];        // per-node partials (emlp1)
__device__ float    g_zero[1536];                  // zero bias (never written)

// ---------------- helpers ----------------
__device__ __forceinline__ float gelu_f(float x) {
    return 0.5f * x * (1.0f + erff(x * 0.70710678118654752440f));
}
__device__ __forceinline__ unsigned f2u(float f) {
    unsigned u = __float_as_uint(f);
    return (u & 0x80000000u) ? ~u : (u | 0x80000000u);
}
__device__ __forceinline__ float u2f(unsigned u) {
    return (u & 0x80000000u) ? __uint_as_float(u & 0x7fffffffu) : __uint_as_float(~u);
}
__device__ __forceinline__ float tf32f(float x) {
    unsigned r;
    asm("cvt.rna.tf32.f32 %0, %1;" : "=r"(r) : "f"(x));
    return __uint_as_float(r);
}
__device__ __forceinline__ float4 tf32f4(float4 v) {
    return make_float4(tf32f(v.x), tf32f(v.y), tf32f(v.z), tf32f(v.w));
}
__device__ __forceinline__ void mma_tf32(float* d, const unsigned* a, const unsigned* b) {
    asm volatile(
        "mma.sync.aligned.m16n8k8.row.col.f32.tf32.tf32.f32 "
        "{%0,%1,%2,%3}, {%4,%5,%6,%7}, {%8,%9}, {%0,%1,%2,%3};"
        : "+f"(d[0]), "+f"(d[1]), "+f"(d[2]), "+f"(d[3])
        : "r"(a[0]), "r"(a[1]), "r"(a[2]), "r"(a[3]), "r"(b[0]), "r"(b[1]));
}

// ---------------- small kernels ----------------
__global__ void pack_wa(const float* __restrict__ aW) {
    int i = blockIdx.x * blockDim.x + threadIdx.x;
    if (i >= LL * HH * CC * DD) return;
    int d = i % DD;
    int c = (i / DD) % CC;
    int h = (i / (DD * CC)) % HH;
    int l = i / (DD * CC * HH);
    g_Wa[((size_t)l * CC + c) * HD + h * DD + d] = aW[i];
}

// g_WU1[l][k][j]: j<512 -> aW(h=j/128, c=k, d=j%128); 512<=j<1024 -> aW(h=(j-512)/128, c=128+k, d);
// 1024<=j<1152 -> nW1[l][k][j-1024]; 1152<=j<1280 -> nW1[l][128+k][j-1152]
__global__ void pack_u1(const float* __restrict__ aW, const float* __restrict__ nW1) {
    int i = blockIdx.x * blockDim.x + threadIdx.x;
    if (i >= LL * DD * 1280) return;
    int j = i % 1280;
    int k = (i / 1280) % DD;
    int l = i / (1280 * DD);
    float v;
    if (j < 1024) {
        int c = (j < 512) ? k : (128 + k);
        int jj = j & 511;
        int h = jj >> 7, d = jj & 127;
        v = aW[(((size_t)l * HH + h) * CC + c) * DD + d];
    } else {
        int c = (j < 1152) ? k : (128 + k);
        int d = (j - 1024) & 127;
        v = nW1[((size_t)l * CC + c) * DD + d];
    }
    g_WU1[i] = v;
}

__global__ void pack_u2(const float* __restrict__ eW1) {
    int i = blockIdx.x * blockDim.x + threadIdx.x;
    if (i >= LL * DD * 256) return;
    int j = i % 256;
    int k = (i / 256) % DD;
    int l = i / (256 * DD);
    int c = (j < 128) ? k : (128 + k);
    g_WU2[i] = eW1[((size_t)l * CC + c) * DE + (j & 127)];
}

__global__ void node_embed(const int* __restrict__ seq, const float* __restrict__ emb) {
    int i = blockIdx.x * blockDim.x + threadIdx.x;
    if (i < NN * DD) g_nodes[i] = emb[seq[i / DD] * DD + (i % DD)];
}

__global__ void edge_init(const float* __restrict__ dist,
                          const float* __restrict__ W, const float* __restrict__ b) {
    int e = blockIdx.x;
    int t = threadIdx.x;
    __shared__ float rbf[16];
    if (t < 16) {
        float mu = 2.0f + (20.0f / 15.0f) * (float)t;
        float z = (dist[e] - mu) * (1.0f / 1.25f);
        rbf[t] = expf(-z * z) + 1e-8f;
    }
    __syncthreads();
    float acc = b[t];
#pragma unroll
    for (int k = 0; k < 16; k++) acc = fmaf(rbf[k], W[k * DE + t], acc);
    g_eattr[(size_t)e * DE + t] = acc;
}

__global__ void smax_init() {
    int i = blockIdx.x * blockDim.x + threadIdx.x;
    if (i < NN * HH) { g_smaxu[i] = 0u; g_norm[i] = 0.0f; }
}

__global__ void smax_atomic(const int* __restrict__ snk) {
    int i = blockIdx.x * blockDim.x + threadIdx.x;
    if (i >= EE * HH) return;
    int e = i / HH, h = i % HH;
    atomicMax(&g_smaxu[snk[e] * HH + h], f2u(g_scores[i]));
}

__global__ void att_kernel(const int* __restrict__ snk) {
    int i = blockIdx.x * blockDim.x + threadIdx.x;
    if (i >= EE * HH) return;
    int e = i / HH, h = i % HH;
    int s = snk[e];
    float a = expf(g_scores[i] - u2f(g_smaxu[s * HH + h]));
    g_att[i] = a;
    atomicAdd(&g_norm[s * HH + h], a + 1e-12f);
}

__global__ void recip_norm() {
    int i = blockIdx.x * blockDim.x + threadIdx.x;
    if (i < NN * HH) g_norm[i] = 1.0f / g_norm[i];
}

__global__ void zero_agg() {
    int i = blockIdx.x * blockDim.x + threadIdx.x;
    if (i < NN * HD) g_agg[i] = 0.0f;
}

__global__ void aggregate(const int* __restrict__ snk) {
    int i = blockIdx.x * blockDim.x + threadIdx.x;   // over EE*32 (float4 lanes)
    if (i >= EE * 32) return;
    int e = i >> 5;
    int d4 = i & 31;
    float4 v = ((const float4*)g_nupd)[(size_t)e * 32 + d4];
    int s = snk[e];
    float4 w = *(const float4*)(g_att + e * 4);
    float4 rn = *(const float4*)(g_norm + s * 4);
    float4* base = (float4*)(g_agg + (size_t)s * HD) + d4;
    float c0 = w.x * rn.x, c1 = w.y * rn.y, c2 = w.z * rn.z, c3 = w.w * rn.w;
    atomicAdd(base,      make_float4(c0 * v.x, c0 * v.y, c0 * v.z, c0 * v.w));
    atomicAdd(base + 32, make_float4(c1 * v.x, c1 * v.y, c1 * v.z, c1 * v.w));
    atomicAdd(base + 64, make_float4(c2 * v.x, c2 * v.y, c2 * v.z, c2 * v.w));
    atomicAdd(base + 96, make_float4(c3 * v.x, c3 * v.y, c3 * v.z, c3 * v.w));
}

__global__ void ln_kernel(const float* __restrict__ A, const float* __restrict__ R,
                          const float* __restrict__ g, const float* __restrict__ b,
                          float* __restrict__ out) {
    int r = blockIdx.x;
    int t = threadIdx.x;
    float x = A[(size_t)r * DD + t] + R[(size_t)r * DD + t];
    float s = x;
#pragma unroll
    for (int o = 16; o > 0; o >>= 1) s += __shfl_xor_sync(0xffffffffu, s, o);
    __shared__ float ws[4], ws2[4];
    if ((t & 31) == 0) ws[t >> 5] = s;
    __syncthreads();
    float mean = (ws[0] + ws[1] + ws[2] + ws[3]) * (1.0f / DD);
    float dx = x - mean;
    float v = dx * dx;
#pragma unroll
    for (int o = 16; o > 0; o >>= 1) v += __shfl_xor_sync(0xffffffffu, v, o);
    if ((t & 31) == 0) ws2[t >> 5] = v;
    __syncthreads();
    float var = (ws2[0] + ws2[1] + ws2[2] + ws2[3]) * (1.0f / DD);
    out[(size_t)r * DD + t] = dx * (1.0f / sqrtf(var + 1e-5f)) * g[t] + b[t];
}

__global__ void copy_out(float* __restrict__ out) {
    int i = blockIdx.x * blockDim.x + threadIdx.x;
    if (i < NN * DD) out[i] = g_nodes[i];
    else if (i < NN * DD + EE * DE) out[i] = g_eattr[i - NN * DD];
}

// ---------------- tf32 tensor-core GEMM, double-buffered ----------------
// C[M,N] = act(A@B + bias [+ U[src]+U[snk]]). BM=128, BN=128, BK=16, 256 thr,
// warp tile 64x32. N multiple of 128, K multiple of 16 (and >= 32 for pipeline).
// ADDUV: epilogue adds U[src[r]*ldu + offS + c] + U[snk[r]*ldu + offK + c].
// ATTN:  BN==head width; lrelu then dot(aA) reduced to g_scores directly.
template <int ACT, bool ATTN, bool ADDUV>   // ACT: 0 none, 1 gelu
__global__ void __launch_bounds__(256) gemm_tc(
    const float* __restrict__ A, int lda,
    const float* __restrict__ B, int ldb,
    const float* __restrict__ bias,
    const float* __restrict__ aA, const float* __restrict__ aAb,
    const int* __restrict__ srcI, const int* __restrict__ snkI,
    const float* __restrict__ U, int ldu, int offS, int offK,
    float* __restrict__ C, int ldc, int M, int K) {
    __shared__ float As[2][128][20];
    __shared__ float Bs[2][16][136];
    __shared__ float sred[128][5];
    const int tid = threadIdx.x;
    const int row0 = blockIdx.y * 128, col0 = blockIdx.x * 128;
    const int wid = tid >> 5, lane = tid & 31, g = lane >> 2, tig = lane & 3;
    const int wm0 = (wid >> 2) * 64, wn0 = (wid & 3) * 32;

    const int arow = tid >> 2, acol = (tid & 3) * 4;
    const int ag0 = min(row0 + arow, M - 1);
    const int ag1 = min(row0 + arow + 64, M - 1);
    const int brow = tid >> 5, bcol = (tid & 31) * 4;

    const float* Ap0 = A + (size_t)ag0 * lda + acol;
    const float* Ap1 = A + (size_t)ag1 * lda + acol;
    const float* Bp  = B + (size_t)brow * ldb + col0 + bcol;

    float4 ar0 = *(const float4*)Ap0;
    float4 ar1 = *(const float4*)Ap1;
    float4 br0 = *(const float4*)Bp;
    float4 br1 = *(const float4*)(Bp + (size_t)8 * ldb);
    *(float4*)&As[0][arow][acol]      = tf32f4(ar0);
    *(float4*)&As[0][arow + 64][acol] = tf32f4(ar1);
    *(float4*)&Bs[0][brow][bcol]      = tf32f4(br0);
    *(float4*)&Bs[0][brow + 8][bcol]  = tf32f4(br1);
    __syncthreads();

    float acc[4][4][4] = {};
    int buf = 0;
    for (int k0 = 0; k0 < K; k0 += 16, buf ^= 1) {
        const bool more = (k0 + 16) < K;
        if (more) {
            ar0 = *(const float4*)(Ap0 + k0 + 16);
            ar1 = *(const float4*)(Ap1 + k0 + 16);
            br0 = *(const float4*)(Bp + (size_t)(k0 + 16) * ldb);
            br1 = *(const float4*)(Bp + (size_t)(k0 + 24) * ldb);
        }
#pragma unroll
        for (int ks = 0; ks < 16; ks += 8) {
            unsigned af[4][4], bf[4][2];
#pragma unroll
            for (int mt = 0; mt < 4; mt++) {
                int r = wm0 + mt * 16 + g;
                af[mt][0] = __float_as_uint(As[buf][r][ks + tig]);
                af[mt][1] = __float_as_uint(As[buf][r + 8][ks + tig]);
                af[mt][2] = __float_as_uint(As[buf][r][ks + tig + 4]);
                af[mt][3] = __float_as_uint(As[buf][r + 8][ks + tig + 4]);
            }
#pragma unroll
            for (int nt = 0; nt < 4; nt++) {
                int c = wn0 + nt * 8 + g;
                bf[nt][0] = __float_as_uint(Bs[buf][ks + tig][c]);
                bf[nt][1] = __float_as_uint(Bs[buf][ks + tig + 4][c]);
            }
#pragma unroll
            for (int mt = 0; mt < 4; mt++)
#pragma unroll
                for (int nt = 0; nt < 4; nt++)
                    mma_tf32(acc[mt][nt], af[mt], bf[nt]);
        }
        if (more) {
            *(float4*)&As[buf ^ 1][arow][acol]      = tf32f4(ar0);
            *(float4*)&As[buf ^ 1][arow + 64][acol] = tf32f4(ar1);
            *(float4*)&Bs[buf ^ 1][brow][bcol]      = tf32f4(br0);
            *(float4*)&Bs[buf ^ 1][brow + 8][bcol]  = tf32f4(br1);
        }
        __syncthreads();
    }

#pragma unroll
    for (int mt = 0; mt < 4; mt++) {
#pragma unroll
        for (int i2 = 0; i2 < 2; i2++) {
            int rl = wm0 + mt * 16 + i2 * 8 + g;
            int gr = row0 + rl;
            int grc = min(gr, M - 1);
            int sI = 0, kI = 0;
            if (ADDUV) { sI = srcI[grc]; kI = snkI[grc]; }
            float p = 0.0f;
#pragma unroll
            for (int nt = 0; nt < 4; nt++) {
                int gc = col0 + wn0 + nt * 8 + 2 * tig;
                float2 bb = *(const float2*)&bias[gc];
                float v0 = acc[mt][nt][i2 * 2 + 0] + bb.x;
                float v1 = acc[mt][nt][i2 * 2 + 1] + bb.y;
                if (ADDUV) {
                    float2 us = *(const float2*)&U[(size_t)sI * ldu + offS + gc];
                    float2 uk = *(const float2*)&U[(size_t)kI * ldu + offK + gc];
                    v0 += us.x + uk.x;
                    v1 += us.y + uk.y;
                }
                if (ATTN) {
                    v0 = (v0 > 0.0f) ? v0 : 0.2f * v0;
                    v1 = (v1 > 0.0f) ? v1 : 0.2f * v1;
                    float2 a2 = *(const float2*)&aA[gc];
                    p = fmaf(v0, a2.x, p);
                    p = fmaf(v1, a2.y, p);
                } else {
                    if (ACT == 1) { v0 = gelu_f(v0); v1 = gelu_f(v1); }
                    if (gr < M) *(float2*)&C[(size_t)gr * ldc + gc] = make_float2(v0, v1);
                }
            }
            if (ATTN) {
                p += __shfl_xor_sync(0xffffffffu, p, 1);
                p += __shfl_xor_sync(0xffffffffu, p, 2);
                if (tig == 0) sred[rl][wid & 3] = p;
            }
        }
    }
    if (ATTN) {
        __syncthreads();
        if (tid < 128) {
            int gr = row0 + tid;
            if (gr < M) {
                int head = col0 >> 7;
                g_scores[gr * HH + head] =
                    sred[tid][0] + sred[tid][1] + sred[tid][2] + sred[tid][3] + aAb[head];
            }
        }
    }
}

// ---------------- host ----------------
static inline void* sym(const void* s) {
    void* p = nullptr;
    cudaGetSymbolAddress(&p, s);
    return p;
}

extern "C" void kernel_launch(void* const* d_in, const int* in_sizes, int n_in,
                              void* d_out, int out_size) {
    const int*   seq      = (const int*)d_in[0];
    const int*   eidx     = (const int*)d_in[1];
    const float* dist     = (const float*)d_in[2];
    const float* seq_emb  = (const float*)d_in[3];
    const float* elW      = (const float*)d_in[4];
    const float* elb      = (const float*)d_in[5];
    const float* aW_W     = (const float*)d_in[6];
    const float* aW_b     = (const float*)d_in[7];
    const float* aA_W     = (const float*)d_in[8];
    const float* aA_b     = (const float*)d_in[9];
    const float* nW1 = (const float*)d_in[10]; const float* nb1 = (const float*)d_in[11];
    const float* nW2 = (const float*)d_in[12]; const float* nb2 = (const float*)d_in[13];
    const float* nW3 = (const float*)d_in[14]; const float* nb3 = (const float*)d_in[15];
    const float* dW1 = (const float*)d_in[16]; const float* db1 = (const float*)d_in[17];
    const float* dW2 = (const float*)d_in[18]; const float* db2 = (const float*)d_in[19];
    const float* eW1 = (const float*)d_in[20]; const float* eb1 = (const float*)d_in[21];
    const float* eW2 = (const float*)d_in[22]; const float* eb2 = (const float*)d_in[23];
    const float* eW3 = (const float*)d_in[24]; const float* eb3 = (const float*)d_in[25];
    const float* agW = (const float*)d_in[26]; const float* agb = (const float*)d_in[27];
    const float* n1g = (const float*)d_in[28]; const float* n1b = (const float*)d_in[29];
    const float* eg  = (const float*)d_in[30]; const float* eb  = (const float*)d_in[31];

    const int* srcp = eidx;
    const int* snkp = eidx + EE;

    float* t1     = (float*)sym(g_t1);
    float* t2     = (float*)sym(g_t2);
    float* nupd   = (float*)sym(g_nupd);
    float* agg    = (float*)sym(g_agg);
    float* nodes  = (float*)sym(g_nodes);
    float* upd    = (float*)sym(g_upd);
    float* dense  = (float*)sym(g_dense);
    float* dense2 = (float*)sym(g_dense2);
    float* Wa     = (float*)sym(g_Wa);
    float* WU1    = (float*)sym(g_WU1);
    float* WU2    = (float*)sym(g_WU2);
    float* U1     = (float*)sym(g_U1);
    float* U2     = (float*)sym(g_U2);
    float* zerob  = (float*)sym(g_zero);
    float* eattr  = (float*)sym(g_eattr);

    const int GME = (EE + 127) / 128;
    const int GMN = (NN + 127) / 128;

    {
        pack_wa<<<(LL * HH * CC * DD + 255) / 256, 256>>>(aW_W);
        pack_u1<<<(LL * DD * 1280 + 255) / 256, 256>>>(aW_W, nW1);
        pack_u2<<<(LL * DD * 256 + 255) / 256, 256>>>(eW1);
        node_embed<<<(NN * DD + 255) / 256, 256>>>(seq, seq_emb);
        edge_init<<<EE, 128>>>(dist, elW, elb);
    }

    for (int l = 0; l < LL; l++) {
        // per-node partials for attn + nmlp1 (old nodes)
        gemm_tc<0, false, false><<<dim3(10, GMN), 256>>>(
            nodes, DD, WU1 + (size_t)l * DD * 1280, 1280, zerob, nullptr, nullptr,
            nullptr, nullptr, nullptr, 0, 0, 0, U1, 1280, NN, DD);

        // attention scores: eattr @ Wa_e + U1 gathers, lrelu, dot(aA)
        gemm_tc<0, true, true><<<dim3(4, GME), 256>>>(
            eattr, DE, Wa + ((size_t)l * CC + 256) * HD, HD, aW_b + l * HD,
            aA_W + l * HD, aA_b + l * HH,
            srcp, snkp, U1, 1280, 0, 512, nullptr, 0, EE, DD);

        // nmlp: W1 (edge part + U1 gathers), then W2, W3
        gemm_tc<1, false, true><<<dim3(1, GME), 256>>>(
            eattr, DE, nW1 + ((size_t)l * CC + 256) * DD, DD, nb1 + l * DD,
            nullptr, nullptr, srcp, snkp, U1, 1280, 1024, 1152, t1, DD, EE, DD);
        gemm_tc<1, false, false><<<dim3(1, GME), 256>>>(
            t1, DD, nW2 + (size_t)l * DD * DD, DD, nb2 + l * DD, nullptr, nullptr,
            nullptr, nullptr, nullptr, 0, 0, 0, t2, DD, EE, DD);
        gemm_tc<0, false, false><<<dim3(1, GME), 256>>>(
            t2, DD, nW3 + (size_t)l * DD * DD, DD, nb3 + l * DD, nullptr, nullptr,
            nullptr, nullptr, nullptr, 0, 0, 0, nupd, DD, EE, DD);

        // scatter softmax over sink nodes
        smax_init<<<(NN * HH + 255) / 256, 256>>>();
        smax_atomic<<<(EE * HH + 255) / 256, 256>>>(snkp);
        att_kernel<<<(EE * HH + 255) / 256, 256>>>(snkp);
        recip_norm<<<(NN * HH + 255) / 256, 256>>>();

        // aggregation
        zero_agg<<<(NN * HD + 255) / 256, 256>>>();
        aggregate<<<(EE * 32 + 255) / 256, 256>>>(snkp);

        // node update + LN + dense MLP + LN
        gemm_tc<0, false, false><<<dim3(1, GMN), 256>>>(
            agg, HD, agW + (size_t)l * HD * DD, DD, agb + l * DD, nullptr, nullptr,
            nullptr, nullptr, nullptr, 0, 0, 0, upd, DD, NN, HD);
        ln_kernel<<<NN, 128>>>(nodes, upd, n1g + l * DD, n1b + l * DD, nodes);
        gemm_tc<1, false, false><<<dim3(4, GMN), 256>>>(
            nodes, DD, dW1 + (size_t)l * DD * D4, D4, db1 + l * D4, nullptr, nullptr,
            nullptr, nullptr, nullptr, 0, 0, 0, dense, D4, NN, DD);
        gemm_tc<0, false, false><<<dim3(1, GMN), 256>>>(
            dense, D4, dW2 + (size_t)l * D4 * DD, DD, db2 + l * DD, nullptr, nullptr,
            nullptr, nullptr, nullptr, 0, 0, 0, dense2, DD, NN, D4);
        ln_kernel<<<NN, 128>>>(dense2, upd, n1g + l * DD, n1b + l * DD, nodes);

        // per-node partials for emlp1 (new nodes)
        gemm_tc<0, false, false><<<dim3(2, GMN), 256>>>(
            nodes, DD, WU2 + (size_t)l * DD * 256, 256, zerob, nullptr, nullptr,
            nullptr, nullptr, nullptr, 0, 0, 0, U2, 256, NN, DD);

        // edge MLP: W1 (edge part + U2 gathers), W2, W3, LN
        gemm_tc<1, false, true><<<dim3(1, GME), 256>>>(
            eattr, DE, eW1 + ((size_t)l * CC + 256) * DE, DE, eb1 + l * DE,
            nullptr, nullptr, srcp, snkp, U2, 256, 0, 128, t1, DE, EE, DD);
        gemm_tc<1, false, false><<<dim3(1, GME), 256>>>(
            t1, DE, eW2 + (size_t)l * DE * DE, DE, eb2 + l * DE, nullptr, nullptr,
            nullptr, nullptr, nullptr, 0, 0, 0, t2, DE, EE, DE);
        gemm_tc<0, false, false><<<dim3(1, GME), 256>>>(
            t2, DE, eW3 + (size_t)l * DE * DE, DE, eb3 + l * DE, nullptr, nullptr,
            nullptr, nullptr, nullptr, 0, 0, 0, nupd, DE, EE, DE);
        ln_kernel<<<EE, 128>>>(eattr, nupd, eg + l * DE, eb + l * DE, eattr);
    }

    copy_out<<<(NN * DD + EE * DE + 255) / 256, 256>>>((float*)d_out);
}